// round 1
// baseline (speedup 1.0000x reference)
#include <cuda_runtime.h>
#include <math.h>

#define NB  16
#define SLQ 2048
#define SLK 2048
#define SDQ 768
#define SDK 1024

// Scratch: __device__ globals (allocation inside kernel_launch is forbidden).
__device__ float g_Qp[(size_t)NB * SLQ * SDK];   // projected Q  [B, LQ, DK]
__device__ float g_Kp[(size_t)NB * SLK * SDK];   // projected K  [B, LK, DK]
__device__ float g_Vp[(size_t)NB * SLK * SDK];   // projected V  [B, LK, DK]
__device__ float g_S [(size_t)NB * SLQ * SLK];   // scores/weights [B, LQ, LK]

// ---------------------------------------------------------------------------
// Tiled SGEMM: C = alpha * A @ op(B) (+ bias row-broadcast)
//   A: [M,K] row-major
//   B: TRANSB ? [N,K] : [K,N] row-major
// 128x128 CTA tile, BK=16, 256 threads, 8x8 per-thread micro-tile.
// All problem dims divide the tile sizes evenly -> no bounds checks.
// ---------------------------------------------------------------------------
template<bool TRANSB, bool HASBIAS>
__global__ void __launch_bounds__(256, 2) sgemm_kernel(
    const float* __restrict__ Ag, const float* __restrict__ Bg,
    const float* __restrict__ bias, float* __restrict__ Cg,
    int M, int N, int K, float alpha,
    long batchA, long batchB, long batchC)
{
    constexpr int BM = 128, BN = 128, BK = 16;
    __shared__ float As[BK][BM + 4];
    __shared__ float Bs[BK][BN + 4];

    const float* A  = Ag + (long)blockIdx.z * batchA;
    const float* Bp = Bg + (long)blockIdx.z * batchB;
    float*       C  = Cg + (long)blockIdx.z * batchC;

    const int tid  = threadIdx.x;
    const int row0 = blockIdx.y * BM;
    const int col0 = blockIdx.x * BN;
    const int tx   = tid & 15;   // column group (8 cols)
    const int ty   = tid >> 4;   // row group (8 rows)

    // K-major tile loads (A always; B when TRANSB): 128 rows x 16 cols
    const int a_row  = tid >> 2;        // 0..63
    const int a_col4 = (tid & 3) << 2;  // 0,4,8,12
    // N-major tile load (B when !TRANSB): 16 rows x 128 cols
    const int b_row  = tid >> 5;        // 0..7
    const int b_col4 = (tid & 31) << 2; // 0..124

    float acc[8][8];
    #pragma unroll
    for (int i = 0; i < 8; i++)
        #pragma unroll
        for (int j = 0; j < 8; j++) acc[i][j] = 0.f;

    for (int k0 = 0; k0 < K; k0 += BK) {
        // Load A tile, store transposed: As[k][m]
        #pragma unroll
        for (int i = 0; i < 2; i++) {
            int r = a_row + i * 64;
            float4 v = *reinterpret_cast<const float4*>(
                A + (long)(row0 + r) * K + (k0 + a_col4));
            As[a_col4 + 0][r] = v.x;
            As[a_col4 + 1][r] = v.y;
            As[a_col4 + 2][r] = v.z;
            As[a_col4 + 3][r] = v.w;
        }
        if (TRANSB) {
            // B is [N,K]: load rows (n), cols (k); store Bs[k][n]
            #pragma unroll
            for (int i = 0; i < 2; i++) {
                int r = a_row + i * 64;
                float4 v = *reinterpret_cast<const float4*>(
                    Bp + (long)(col0 + r) * K + (k0 + a_col4));
                Bs[a_col4 + 0][r] = v.x;
                Bs[a_col4 + 1][r] = v.y;
                Bs[a_col4 + 2][r] = v.z;
                Bs[a_col4 + 3][r] = v.w;
            }
        } else {
            // B is [K,N]: direct coalesced copy
            #pragma unroll
            for (int i = 0; i < 2; i++) {
                int r = b_row + i * 8;
                float4 v = *reinterpret_cast<const float4*>(
                    Bp + (long)(k0 + r) * N + (col0 + b_col4));
                *reinterpret_cast<float4*>(&Bs[r][b_col4]) = v;
            }
        }
        __syncthreads();

        #pragma unroll
        for (int kk = 0; kk < BK; kk++) {
            float a[8], b[8];
            #pragma unroll
            for (int i = 0; i < 8; i++) a[i] = As[kk][ty * 8 + i];
            #pragma unroll
            for (int j = 0; j < 8; j++) b[j] = Bs[kk][tx * 8 + j];
            #pragma unroll
            for (int i = 0; i < 8; i++)
                #pragma unroll
                for (int j = 0; j < 8; j++)
                    acc[i][j] = fmaf(a[i], b[j], acc[i][j]);
        }
        __syncthreads();
    }

    // Epilogue: scale (+bias), vectorized store
    #pragma unroll
    for (int i = 0; i < 8; i++) {
        long r = row0 + ty * 8 + i;
        #pragma unroll
        for (int jj = 0; jj < 2; jj++) {
            int c = col0 + tx * 8 + jj * 4;
            float4 v;
            v.x = acc[i][jj * 4 + 0] * alpha;
            v.y = acc[i][jj * 4 + 1] * alpha;
            v.z = acc[i][jj * 4 + 2] * alpha;
            v.w = acc[i][jj * 4 + 3] * alpha;
            if (HASBIAS) {
                v.x += bias[c + 0];
                v.y += bias[c + 1];
                v.z += bias[c + 2];
                v.w += bias[c + 3];
            }
            *reinterpret_cast<float4*>(C + r * (long)N + c) = v;
        }
    }
}

// ---------------------------------------------------------------------------
// Row softmax over LK=2048. One 256-thread CTA per row; 8 elems/thread kept
// in registers (single read, single write).
// ---------------------------------------------------------------------------
__global__ void __launch_bounds__(256) softmax_kernel(float* __restrict__ S)
{
    float* p = S + (size_t)blockIdx.x * SLK;
    const int tid = threadIdx.x;

    float v[8];
    float m = -1e30f;
    #pragma unroll
    for (int i = 0; i < 8; i++) {
        v[i] = p[tid + i * 256];
        m = fmaxf(m, v[i]);
    }
    #pragma unroll
    for (int off = 16; off; off >>= 1)
        m = fmaxf(m, __shfl_xor_sync(0xffffffffu, m, off));

    __shared__ float red[8];
    if ((tid & 31) == 0) red[tid >> 5] = m;
    __syncthreads();
    float m2 = red[0];
    #pragma unroll
    for (int i = 1; i < 8; i++) m2 = fmaxf(m2, red[i]);
    __syncthreads();

    float s = 0.f;
    #pragma unroll
    for (int i = 0; i < 8; i++) {
        v[i] = __expf(v[i] - m2);
        s += v[i];
    }
    #pragma unroll
    for (int off = 16; off; off >>= 1)
        s += __shfl_xor_sync(0xffffffffu, s, off);
    if ((tid & 31) == 0) red[tid >> 5] = s;
    __syncthreads();
    float tot = 0.f;
    #pragma unroll
    for (int i = 0; i < 8; i++) tot += red[i];

    float inv = 1.f / tot;
    #pragma unroll
    for (int i = 0; i < 8; i++) p[tid + i * 256] = v[i] * inv;
}

// ---------------------------------------------------------------------------
// Launch: 3 projection GEMMs -> scores (NT, scaled) -> softmax -> weights@V
// All on the default stream; no sync, no allocation -> graph-capturable.
// ---------------------------------------------------------------------------
extern "C" void kernel_launch(void* const* d_in, const int* in_sizes, int n_in,
                              void* d_out, int out_size)
{
    const float* query = (const float*)d_in[0];
    const float* key   = (const float*)d_in[1];
    const float* Wq    = (const float*)d_in[2];
    const float* bq    = (const float*)d_in[3];
    const float* Wk    = (const float*)d_in[4];
    const float* bk    = (const float*)d_in[5];
    const float* Wv    = (const float*)d_in[6];
    const float* bv    = (const float*)d_in[7];
    float* out = (float*)d_out;

    float *Qp, *Kp, *Vp, *S;
    cudaGetSymbolAddress((void**)&Qp, g_Qp);
    cudaGetSymbolAddress((void**)&Kp, g_Kp);
    cudaGetSymbolAddress((void**)&Vp, g_Vp);
    cudaGetSymbolAddress((void**)&S,  g_S);

    dim3 blk(256);

    // Projections: fold batch into M (inputs are contiguous [B*L, D]).
    {
        dim3 g(SDK / 128, (NB * SLQ) / 128, 1);
        sgemm_kernel<false, true><<<g, blk>>>(query, Wq, bq, Qp,
                                              NB * SLQ, SDK, SDQ, 1.f, 0, 0, 0);
        sgemm_kernel<false, true><<<g, blk>>>(key, Wk, bk, Kp,
                                              NB * SLK, SDK, SDK, 1.f, 0, 0, 0);
        sgemm_kernel<false, true><<<g, blk>>>(key, Wv, bv, Vp,
                                              NB * SLK, SDK, SDK, 1.f, 0, 0, 0);
    }

    // scores = (Qp @ Kp^T) / sqrt(1024); batch via blockIdx.z
    {
        dim3 g(SLK / 128, SLQ / 128, NB);
        sgemm_kernel<true, false><<<g, blk>>>(Qp, Kp, nullptr, S,
                                              SLQ, SLK, SDK, 0.03125f,
                                              (long)SLQ * SDK,
                                              (long)SLK * SDK,
                                              (long)SLQ * SLK);
    }

    // softmax over the last dim
    softmax_kernel<<<NB * SLQ, 256>>>(S);

    // out = weights @ Vp
    {
        dim3 g(SDK / 128, SLQ / 128, NB);
        sgemm_kernel<false, false><<<g, blk>>>(S, Vp, nullptr, out,
                                               SLQ, SDK, SLK, 1.f,
                                               (long)SLQ * SLK,
                                               (long)SLK * SDK,
                                               (long)SLQ * SDK);
    }
}

// round 3
// speedup vs baseline: 2.9593x; 2.9593x over previous
#include <cuda_runtime.h>
#include <cuda_bf16.h>
#include <stdint.h>

typedef __nv_bfloat16 bf16;

#define NB  16
#define SLQ 2048
#define SLK 2048
#define SDQ 768
#define SDK 1024

// ---------------------------------------------------------------------------
// Device-global scratch (no allocation allowed in kernel_launch).
// ---------------------------------------------------------------------------
__device__ bf16 g_qh [(size_t)NB*SLQ*SDQ];   // split(query)
__device__ bf16 g_ql [(size_t)NB*SLQ*SDQ];
__device__ bf16 g_kh [(size_t)NB*SLK*SDK];   // split(key)
__device__ bf16 g_kl [(size_t)NB*SLK*SDK];
__device__ bf16 g_wqh[SDK*SDQ];              // Wq^T split  [1024,768]
__device__ bf16 g_wql[SDK*SDQ];
__device__ bf16 g_wkh[SDK*SDK];              // Wk^T split  [1024,1024]
__device__ bf16 g_wkl[SDK*SDK];
__device__ bf16 g_wvh[SDK*SDK];              // Wv^T split
__device__ bf16 g_wvl[SDK*SDK];
__device__ bf16 g_Qph[(size_t)NB*SLQ*SDK];   // projected Q split [B,Lq,Dk]
__device__ bf16 g_Qpl[(size_t)NB*SLQ*SDK];
__device__ bf16 g_Kph[(size_t)NB*SLK*SDK];   // projected K split [B,Lk,Dk]
__device__ bf16 g_Kpl[(size_t)NB*SLK*SDK];
__device__ bf16 g_Vth[(size_t)NB*SDK*SLK];   // projected V^T split [B,Dk,Lk]
__device__ bf16 g_Vtl[(size_t)NB*SDK*SLK];
__device__ float g_S [(size_t)NB*SLQ*SLK];   // scores fp32
__device__ bf16 g_Sh [(size_t)NB*SLQ*SLK];   // softmax weights split
__device__ bf16 g_Sl [(size_t)NB*SLQ*SLK];

// ---------------------------------------------------------------------------
// PTX helpers — baseline (non-'a') features only: ldmatrix, mma.sync, cp.async
// ---------------------------------------------------------------------------
__device__ __forceinline__ uint32_t smem_u32(const void* p) {
    uint32_t a;
    asm("{ .reg .u64 t; cvta.to.shared.u64 t, %1; cvt.u32.u64 %0, t; }"
        : "=r"(a) : "l"(p));
    return a;
}
__device__ __forceinline__ void cpa16(uint32_t dst, const void* src) {
    asm volatile("cp.async.cg.shared.global [%0], [%1], 16;"
                 :: "r"(dst), "l"(src) : "memory");
}
__device__ __forceinline__ void cpa_commit() {
    asm volatile("cp.async.commit_group;" ::: "memory");
}
template<int N>
__device__ __forceinline__ void cpa_wait() {
    asm volatile("cp.async.wait_group %0;" :: "n"(N) : "memory");
}
__device__ __forceinline__ void ldmx4(uint32_t* r, uint32_t addr) {
    asm volatile("ldmatrix.sync.aligned.m8n8.x4.shared.b16 {%0,%1,%2,%3}, [%4];"
                 : "=r"(r[0]), "=r"(r[1]), "=r"(r[2]), "=r"(r[3]) : "r"(addr));
}
__device__ __forceinline__ void mma16816(float* c, const uint32_t* a, const uint32_t* b) {
    asm volatile(
        "mma.sync.aligned.m16n8k16.row.col.f32.bf16.bf16.f32 "
        "{%0,%1,%2,%3}, {%4,%5,%6,%7}, {%8,%9}, {%0,%1,%2,%3};"
        : "+f"(c[0]), "+f"(c[1]), "+f"(c[2]), "+f"(c[3])
        : "r"(a[0]), "r"(a[1]), "r"(a[2]), "r"(a[3]), "r"(b[0]), "r"(b[1]));
}
__device__ __forceinline__ uint32_t sw128(uint32_t o) { return o ^ ((o >> 3) & 0x70); }

__device__ __forceinline__ uint32_t split_pack(float x, float y, uint32_t& lopack) {
    bf16 hx = __float2bfloat16(x), hy = __float2bfloat16(y);
    bf16 lx = __float2bfloat16(x - __bfloat162float(hx));
    bf16 ly = __float2bfloat16(y - __bfloat162float(hy));
    lopack = (uint32_t)__bfloat16_as_ushort(lx) | ((uint32_t)__bfloat16_as_ushort(ly) << 16);
    return (uint32_t)__bfloat16_as_ushort(hx) | ((uint32_t)__bfloat16_as_ushort(hy) << 16);
}

// ---------------------------------------------------------------------------
// bf16x3 HMMA GEMM:  D[M,N] = alpha * (A @ B^T) (+ bias)
//   A hi/lo [M,K] K-major; B hi/lo [N,K] K-major.
//   CTA 128x128, BK=64 (128B rows, SW128), 2-stage cp.async, 8 warps (2m x 4n),
//   warp tile 64x32, mma.sync.m16n8k16, 3 passes into one fp32 accumulator.
// OUTMODE: 0 = fp32 C;  1 = split bf16 (Chi, Clo)
// BIASMODE: 0 = none; 1 = bias per column; 2 = bias per row
// ---------------------------------------------------------------------------
#define BM 128
#define BN 128
#define BKC 64
#define OFF_AL 16384
#define OFF_BH 32768
#define OFF_BL 49152
#define STAGE  65536
#define GEMM_SMEM (2*STAGE)   // 131072

template<int OUTMODE, int BIASMODE>
__global__ void __launch_bounds__(256, 1) mma_gemm(
    const bf16* __restrict__ Ah, const bf16* __restrict__ Al,
    const bf16* __restrict__ Bh, const bf16* __restrict__ Bl,
    const float* __restrict__ bias,
    float* __restrict__ Cf, bf16* __restrict__ Chi, bf16* __restrict__ Clo,
    int N, int K, float alpha,
    long batchA, long batchB, long batchC)
{
    extern __shared__ char smem[];
    const uint32_t sbase = smem_u32(smem);
    const int tid  = threadIdx.x;
    const int lane = tid & 31;
    const int wid  = tid >> 5;
    const int wm   = wid >> 2;   // 0..1  (m64)
    const int wn   = wid & 3;    // 0..3  (n32)
    const int row0 = blockIdx.y * BM;
    const int col0 = blockIdx.x * BN;
    const size_t zA = (size_t)blockIdx.z * batchA;
    const size_t zB = (size_t)blockIdx.z * batchB;
    const size_t zC = (size_t)blockIdx.z * batchC;

    const int r8 = tid >> 3;              // 0..31
    const uint32_t cb = (tid & 7) * 16;   // byte offset within 128B row

    auto load_stage = [&](int s, int k0) {
        const uint32_t st = sbase + s * STAGE;
        #pragma unroll
        for (int i = 0; i < 4; i++) {
            int r = r8 + i * 32;
            size_t go = (size_t)(row0 + r) * K + k0;
            uint32_t so = sw128((uint32_t)(r * 128) + cb);
            cpa16(st + so,          (const char*)(Ah + zA + go) + cb);
            cpa16(st + OFF_AL + so, (const char*)(Al + zA + go) + cb);
        }
        #pragma unroll
        for (int i = 0; i < 4; i++) {
            int r = r8 + i * 32;
            size_t go = (size_t)(col0 + r) * K + k0;
            uint32_t so = sw128((uint32_t)(r * 128) + cb);
            cpa16(st + OFF_BH + so, (const char*)(Bh + zB + go) + cb);
            cpa16(st + OFF_BL + so, (const char*)(Bl + zB + go) + cb);
        }
        cpa_commit();
    };

    float c[4][4][4];
    #pragma unroll
    for (int i = 0; i < 4; i++)
        #pragma unroll
        for (int j = 0; j < 4; j++)
            #pragma unroll
            for (int k = 0; k < 4; k++) c[i][j][k] = 0.f;

    const int nk = K / BKC;
    load_stage(0, 0);
    load_stage(1, BKC);

    // per-lane ldmatrix address components
    const int a_r = ((lane >> 3) & 1) * 8 + (lane & 7);  // row within m16 tile
    const int a_k = ((lane >> 4) & 1) * 16;              // k-byte within 32B
    const int b_r = ((lane >> 4) & 1) * 8 + (lane & 7);
    const int b_k = ((lane >> 3) & 1) * 16;

    for (int i = 0; i < nk; i++) {
        if (i + 1 < nk) cpa_wait<1>(); else cpa_wait<0>();
        __syncthreads();

        const uint32_t st = sbase + (i & 1) * STAGE;
        #pragma unroll
        for (int ks = 0; ks < 4; ks++) {
            uint32_t ah[4][4], al[4][4];
            #pragma unroll
            for (int fm = 0; fm < 4; fm++) {
                int row = wm * 64 + fm * 16 + a_r;
                uint32_t so = sw128((uint32_t)(row * 128) + ks * 32 + a_k);
                ldmx4(ah[fm], st + so);
                ldmx4(al[fm], st + OFF_AL + so);
            }
            uint32_t bh_[2][4], bl_[2][4];
            #pragma unroll
            for (int g = 0; g < 2; g++) {
                int row = wn * 32 + g * 16 + b_r;
                uint32_t so = sw128((uint32_t)(row * 128) + ks * 32 + b_k);
                ldmx4(bh_[g], st + OFF_BH + so);
                ldmx4(bl_[g], st + OFF_BL + so);
            }
            #pragma unroll
            for (int fm = 0; fm < 4; fm++)
                #pragma unroll
                for (int fn = 0; fn < 4; fn++) {
                    const uint32_t* b2h = &bh_[fn >> 1][(fn & 1) * 2];
                    const uint32_t* b2l = &bl_[fn >> 1][(fn & 1) * 2];
                    mma16816(c[fm][fn], ah[fm], b2h);
                    mma16816(c[fm][fn], ah[fm], b2l);
                    mma16816(c[fm][fn], al[fm], b2h);
                }
        }
        if (i + 2 < nk) {
            __syncthreads();               // all warps done reading buf (i&1)
            load_stage(i & 1, (i + 2) * BKC);
        }
    }

    // ---- epilogue: fragments -> global ---------------------------------
    #pragma unroll
    for (int fm = 0; fm < 4; fm++)
        #pragma unroll
        for (int fn = 0; fn < 4; fn++) {
            int row = row0 + wm * 64 + fm * 16 + (lane >> 2);
            int col = col0 + wn * 32 + fn * 8 + (lane & 3) * 2;
            float v0 = c[fm][fn][0] * alpha, v1 = c[fm][fn][1] * alpha;
            float v2 = c[fm][fn][2] * alpha, v3 = c[fm][fn][3] * alpha;
            if (BIASMODE == 1) {
                float b0 = bias[col], b1 = bias[col + 1];
                v0 += b0; v1 += b1; v2 += b0; v3 += b1;
            }
            if (BIASMODE == 2) {
                float rb0 = bias[row], rb1 = bias[row + 8];
                v0 += rb0; v1 += rb0; v2 += rb1; v3 += rb1;
            }
            size_t o0 = zC + (size_t)row * N + col;
            size_t o1 = zC + (size_t)(row + 8) * N + col;
            if (OUTMODE == 0) {
                *(float2*)(Cf + o0) = make_float2(v0, v1);
                *(float2*)(Cf + o1) = make_float2(v2, v3);
            } else {
                uint32_t lo0, lo1;
                uint32_t hi0 = split_pack(v0, v1, lo0);
                uint32_t hi1 = split_pack(v2, v3, lo1);
                *(uint32_t*)(Chi + o0) = hi0;
                *(uint32_t*)(Clo + o0) = lo0;
                *(uint32_t*)(Chi + o1) = hi1;
                *(uint32_t*)(Clo + o1) = lo1;
            }
        }
}

// ---------------------------------------------------------------------------
// Elementwise split: fp32 -> (hi, lo) bf16.  n multiple of 4.
// ---------------------------------------------------------------------------
__global__ void split_kernel(const float* __restrict__ x,
                             bf16* __restrict__ hi, bf16* __restrict__ lo, size_t n)
{
    size_t i = ((size_t)blockIdx.x * blockDim.x + threadIdx.x) * 4;
    if (i >= n) return;
    float4 v = *(const float4*)(x + i);
    uint32_t l0, l1;
    uint32_t h0 = split_pack(v.x, v.y, l0);
    uint32_t h1 = split_pack(v.z, v.w, l1);
    *(uint2*)(hi + i) = make_uint2(h0, h1);
    *(uint2*)(lo + i) = make_uint2(l0, l1);
}

// ---------------------------------------------------------------------------
// Transposed split: W [K,N] fp32 -> Wt hi/lo [N,K] bf16.
// ---------------------------------------------------------------------------
__global__ void transpose_split_kernel(const float* __restrict__ W,
                                       bf16* __restrict__ hi, bf16* __restrict__ lo,
                                       int K, int N)
{
    __shared__ float t[32][33];
    int n0 = blockIdx.x * 32, k0 = blockIdx.y * 32;
    int x = threadIdx.x, y = threadIdx.y;
    #pragma unroll
    for (int j = 0; j < 32; j += 8)
        t[y + j][x] = W[(size_t)(k0 + y + j) * N + n0 + x];
    __syncthreads();
    #pragma unroll
    for (int j = 0; j < 32; j += 8) {
        float v = t[x][y + j];
        bf16 h = __float2bfloat16(v);
        bf16 l = __float2bfloat16(v - __bfloat162float(h));
        size_t o = (size_t)(n0 + y + j) * K + k0 + x;
        hi[o] = h; lo[o] = l;
    }
}

// ---------------------------------------------------------------------------
// Row softmax over LK=2048; reads fp32, writes split bf16 weights.
// ---------------------------------------------------------------------------
__global__ void __launch_bounds__(256) softmax_kernel(
    const float* __restrict__ S, bf16* __restrict__ Sh, bf16* __restrict__ Sl)
{
    const float* p = S + (size_t)blockIdx.x * SLK;
    const int tid = threadIdx.x;

    float v[8];
    float mx = -1e30f;
    #pragma unroll
    for (int i = 0; i < 8; i++) { v[i] = p[tid + i * 256]; mx = fmaxf(mx, v[i]); }
    #pragma unroll
    for (int off = 16; off; off >>= 1)
        mx = fmaxf(mx, __shfl_xor_sync(0xffffffffu, mx, off));

    __shared__ float red[8];
    if ((tid & 31) == 0) red[tid >> 5] = mx;
    __syncthreads();
    float m2 = red[0];
    #pragma unroll
    for (int i = 1; i < 8; i++) m2 = fmaxf(m2, red[i]);
    __syncthreads();

    float s = 0.f;
    #pragma unroll
    for (int i = 0; i < 8; i++) { v[i] = __expf(v[i] - m2); s += v[i]; }
    #pragma unroll
    for (int off = 16; off; off >>= 1)
        s += __shfl_xor_sync(0xffffffffu, s, off);
    if ((tid & 31) == 0) red[tid >> 5] = s;
    __syncthreads();
    float tot = 0.f;
    #pragma unroll
    for (int i = 0; i < 8; i++) tot += red[i];

    float inv = 1.f / tot;
    size_t base = (size_t)blockIdx.x * SLK + tid;
    #pragma unroll
    for (int i = 0; i < 8; i++) {
        float w = v[i] * inv;
        bf16 h = __float2bfloat16(w);
        bf16 l = __float2bfloat16(w - __bfloat162float(h));
        Sh[base + i * 256] = h;
        Sl[base + i * 256] = l;
    }
}

// ---------------------------------------------------------------------------
// kernel_launch
// ---------------------------------------------------------------------------
extern "C" void kernel_launch(void* const* d_in, const int* in_sizes, int n_in,
                              void* d_out, int out_size)
{
    const float* query = (const float*)d_in[0];
    const float* key   = (const float*)d_in[1];
    const float* Wq    = (const float*)d_in[2];
    const float* bq    = (const float*)d_in[3];
    const float* Wk    = (const float*)d_in[4];
    const float* bk    = (const float*)d_in[5];
    const float* Wv    = (const float*)d_in[6];
    const float* bv    = (const float*)d_in[7];
    float* out = (float*)d_out;

    bf16 *qh,*ql,*kh,*kl,*wqh,*wql,*wkh,*wkl,*wvh,*wvl;
    bf16 *Qph,*Qpl,*Kph,*Kpl,*Vth,*Vtl,*Sh,*Sl;
    float *S;
    cudaGetSymbolAddress((void**)&qh,  g_qh);  cudaGetSymbolAddress((void**)&ql,  g_ql);
    cudaGetSymbolAddress((void**)&kh,  g_kh);  cudaGetSymbolAddress((void**)&kl,  g_kl);
    cudaGetSymbolAddress((void**)&wqh, g_wqh); cudaGetSymbolAddress((void**)&wql, g_wql);
    cudaGetSymbolAddress((void**)&wkh, g_wkh); cudaGetSymbolAddress((void**)&wkl, g_wkl);
    cudaGetSymbolAddress((void**)&wvh, g_wvh); cudaGetSymbolAddress((void**)&wvl, g_wvl);
    cudaGetSymbolAddress((void**)&Qph, g_Qph); cudaGetSymbolAddress((void**)&Qpl, g_Qpl);
    cudaGetSymbolAddress((void**)&Kph, g_Kph); cudaGetSymbolAddress((void**)&Kpl, g_Kpl);
    cudaGetSymbolAddress((void**)&Vth, g_Vth); cudaGetSymbolAddress((void**)&Vtl, g_Vtl);
    cudaGetSymbolAddress((void**)&S,   g_S);
    cudaGetSymbolAddress((void**)&Sh,  g_Sh);  cudaGetSymbolAddress((void**)&Sl,  g_Sl);

    cudaFuncSetAttribute(mma_gemm<0,0>, cudaFuncAttributeMaxDynamicSharedMemorySize, GEMM_SMEM);
    cudaFuncSetAttribute(mma_gemm<1,1>, cudaFuncAttributeMaxDynamicSharedMemorySize, GEMM_SMEM);
    cudaFuncSetAttribute(mma_gemm<1,2>, cudaFuncAttributeMaxDynamicSharedMemorySize, GEMM_SMEM);

    // 1. split inputs
    {
        size_t nq = (size_t)NB * SLQ * SDQ;
        split_kernel<<<(unsigned)((nq/4 + 255)/256), 256>>>(query, qh, ql, nq);
        size_t nkk = (size_t)NB * SLK * SDK;
        split_kernel<<<(unsigned)((nkk/4 + 255)/256), 256>>>(key, kh, kl, nkk);
    }
    // 2. transpose-split weights (W[K,N] -> Wt[N,K])
    transpose_split_kernel<<<dim3(SDK/32, SDQ/32), dim3(32,8)>>>(Wq, wqh, wql, SDQ, SDK);
    transpose_split_kernel<<<dim3(SDK/32, SDK/32), dim3(32,8)>>>(Wk, wkh, wkl, SDK, SDK);
    transpose_split_kernel<<<dim3(SDK/32, SDK/32), dim3(32,8)>>>(Wv, wvh, wvl, SDK, SDK);

    // 3. Q projection (M=B*Lq=32768, N=1024, K=768)
    mma_gemm<1,1><<<dim3(SDK/BN, (NB*SLQ)/BM, 1), 256, GEMM_SMEM>>>(
        qh, ql, wqh, wql, bq, nullptr, Qph, Qpl,
        SDK, SDQ, 1.f, 0, 0, 0);

    // 4. K projection (M=32768, N=1024, K=1024)
    mma_gemm<1,1><<<dim3(SDK/BN, (NB*SLK)/BM, 1), 256, GEMM_SMEM>>>(
        kh, kl, wkh, wkl, bk, nullptr, Kph, Kpl,
        SDK, SDK, 1.f, 0, 0, 0);

    // 5. V projection, transposed output: VpT[b][o][t] (M=1024, N=2048, K=1024)
    mma_gemm<1,2><<<dim3(SLK/BN, SDK/BM, NB), 256, GEMM_SMEM>>>(
        wvh, wvl, kh, kl, bv, nullptr, Vth, Vtl,
        SLK, SDK, 1.f, 0, (long)SLK*SDK, (long)SDK*SLK);

    // 6. scores = (Qp @ Kp^T) / 32  (M=2048, N=2048, K=1024 per batch)
    mma_gemm<0,0><<<dim3(SLK/BN, SLQ/BM, NB), 256, GEMM_SMEM>>>(
        Qph, Qpl, Kph, Kpl, nullptr, S, nullptr, nullptr,
        SLK, SDK, 0.03125f, (long)SLQ*SDK, (long)SLK*SDK, (long)SLQ*SLK);

    // 7. softmax -> split weights
    softmax_kernel<<<NB*SLQ, 256>>>(S, Sh, Sl);

    // 8. out = weights @ Vp  (M=2048, N=1024, K=2048 per batch)
    mma_gemm<0,0><<<dim3(SDK/BN, SLQ/BM, NB), 256, GEMM_SMEM>>>(
        Sh, Sl, Vth, Vtl, nullptr, out, nullptr, nullptr,
        SDK, SLK, 1.f, (long)SLQ*SLK, (long)SDK*SLK, (long)SLQ*SDK);
}